// round 11
// baseline (speedup 1.0000x reference)
#include <cuda_runtime.h>
#include <math.h>

constexpr int   NELEM  = 8192;
constexpr int   NB     = 256;            // psi buckets == blocks
constexpr int   BCAP   = 96;             // slots/bucket (mean 32, +11 sigma)
constexpr int   TPB    = 128;
constexpr int   NBLK   = 256;
constexpr int   EPB    = NELEM / NBLK;   // 32 elements per block (warp 0)
constexpr int   WMARG  = 13;             // 13/256 = 0.0508 > 0.05
constexpr int   WBK    = 2 * WMARG + 1;  // 27 window buckets
constexpr float THRESH = 0.05f;
constexpr float MSEW   = 10.0f;
constexpr float LEPS   = 1e-7f;
constexpr float SENT   = 1.0e9f;

// device scratch; counters self-reset in finalize each replay
__device__ float2   g_bucket[NB][BCAP];
__device__ int      g_bcnt[NB];
__device__ float    g_md[NBLK], g_md2[NBLK], g_mb[NBLK];
__device__ float    g_ps[NBLK];
__device__ int      g_pc[NBLK];
__device__ unsigned g_bar1, g_bar2;

__global__ void __launch_bounds__(TPB)
fused(const float* __restrict__ pred, const float* __restrict__ psi,
      const int* __restrict__ flag, float* __restrict__ out)
{
    __shared__ float2 win[WBK * BCAP];      // 2592 float2 = 20.7 KB
    __shared__ int    scnt[WBK];
    __shared__ float  shs[TPB / 32];
    __shared__ int    shc[TPB / 32];
    __shared__ int    sh_last;

    const int tid  = threadIdx.x;
    const int lane = tid & 31;
    const int wrp  = tid >> 5;
    const int b    = blockIdx.x;

    // ================= phase A: warp 0 preps this block's 32 elements =================
    if (tid < 32) {
        int i = b * EPB + tid;
        float x = __ldg(&pred[i]);
        float y = __ldg(&psi[i]);
        float p = fminf(fmaxf(y, LEPS), 1.0f - LEPS);
        float d = x - __logf(__fdividef(p, 1.0f - p));
        int  bk = min(NB - 1, max(0, (int)(y * (float)NB)));

        int pos = atomicAdd(&g_bcnt[bk], 1);
        if (pos < BCAP) g_bucket[bk][pos] = make_float2(y, d);

        float sd  = d;
        float sd2 = d * d;
        float sb  = fmaxf(x, 0.f) - x * y + __logf(1.0f + __expf(-fabsf(x)));
        #pragma unroll
        for (int o = 16; o > 0; o >>= 1) {
            sd  += __shfl_down_sync(0xffffffffu, sd,  o);
            sd2 += __shfl_down_sync(0xffffffffu, sd2, o);
            sb  += __shfl_down_sync(0xffffffffu, sb,  o);
        }
        if (tid == 0) { g_md[b] = sd; g_md2[b] = sd2; g_mb[b] = sb; }
        __threadfence();
        if (tid == 0) atomicAdd(&g_bar1, 1u);
    }

    // ================= phase B: grid barrier (all blocks resident by design) =========
    if (tid == 0) {
        volatile unsigned* p1 = &g_bar1;
        while (*p1 < (unsigned)NBLK) { }
    }
    __syncthreads();
    __threadfence();

    // ================= phase C: block b scans bucket b's invalid window ==============
    const int cnt_b = min(__ldcg(&g_bcnt[b]), BCAP);
    float2 p0 = __ldcg(&g_bucket[b][lane]);
    float2 p1 = __ldcg(&g_bucket[b][lane + 32]);
    float2 p2 = __ldcg(&g_bucket[b][lane + 64]);
    if (lane      >= cnt_b) p0.x = SENT;
    if (lane + 32 >= cnt_b) p1.x = SENT;
    if (lane + 64 >= cnt_b) p2.x = SENT;

    const int babs0 = b - WMARG;
    if (tid < WBK) {
        int bb = babs0 + tid;
        scnt[tid] = (bb >= 0 && bb < NB) ? min(__ldcg(&g_bcnt[bb]), BCAP) : 0;
    }

    // flat coalesced copy of padded rows (padding copied, never read)
    {
        const int cb0c = max(babs0, 0);
        const int cb1c = min(b + WMARG + 1, NB);
        const int n    = (cb1c - cb0c) * BCAP;
        const int dst0 = (cb0c - babs0) * BCAP;
        const float2* src = &g_bucket[cb0c][0];
        for (int t = tid; t < n; t += TPB) win[dst0 + t] = __ldcg(&src[t]);
    }
    __syncthreads();

    // warp-split of the 27 window buckets: 6/7/7/7
    const int q0 = (WBK * wrp)       >> 2;
    const int q1 = (WBK * (wrp + 1)) >> 2;

    float sacc = 0.f; int cacc = 0;
    for (int bb = q0; bb < q1; ++bb) {
        const int    c    = scnt[bb];
        const float2* base = &win[bb * BCAP];
        const float y0 = p0.x, d0 = p0.y;
        float s0 = 0.f; int c0 = 0;
        #pragma unroll 4
        for (int k = 0; k < c; ++k) {
            float2 pj = base[k];                   // broadcast LDS.64
            float dp = y0 - pj.x;
            float dd = d0 - pj.y;
            if (fabsf(dp) < THRESH) { s0 = fmaf(dd, dd, s0); c0++; }
        }
        sacc += s0; cacc += c0;
        if (cnt_b > 32) {
            const float y1 = p1.x, d1 = p1.y;
            float s1 = 0.f; int c1 = 0;
            #pragma unroll 4
            for (int k = 0; k < c; ++k) {
                float2 pj = base[k];
                float dp = y1 - pj.x;
                float dd = d1 - pj.y;
                if (fabsf(dp) < THRESH) { s1 = fmaf(dd, dd, s1); c1++; }
            }
            sacc += s1; cacc += c1;
        }
        if (cnt_b > 64) {
            const float y2 = p2.x, d2 = p2.y;
            float s2 = 0.f; int c2 = 0;
            #pragma unroll 4
            for (int k = 0; k < c; ++k) {
                float2 pj = base[k];
                float dp = y2 - pj.x;
                float dd = d2 - pj.y;
                if (fabsf(dp) < THRESH) { s2 = fmaf(dd, dd, s2); c2++; }
            }
            sacc += s2; cacc += c2;
        }
    }

    // ---- block reduction -> slot ----
    #pragma unroll
    for (int o = 16; o > 0; o >>= 1) {
        sacc += __shfl_down_sync(0xffffffffu, sacc, o);
        cacc += __shfl_down_sync(0xffffffffu, cacc, o);
    }
    if (lane == 0) { shs[wrp] = sacc; shc[wrp] = cacc; }
    __syncthreads();
    if (tid == 0) {
        float fs = 0.f; int fc = 0;
        #pragma unroll
        for (int w = 0; w < TPB / 32; ++w) { fs += shs[w]; fc += shc[w]; }
        g_ps[b] = fs; g_pc[b] = fc;
        __threadfence();
        sh_last = (atomicAdd(&g_bar2, 1u) == (unsigned)(NBLK - 1));
        if (sh_last) __threadfence();
    }
    __syncthreads();
    if (!sh_last) return;

    // ================= finalize in last-arriving block =================
    double dsi = 0.0, ds = 0.0, ds2 = 0.0, db = 0.0;
    long long ci = 0;
    for (int k = tid; k < NBLK; k += TPB) {
        dsi += (double)__ldcg(&g_ps[k]);
        ci  += (long long)__ldcg(&g_pc[k]);
        ds  += (double)__ldcg(&g_md[k]);
        ds2 += (double)__ldcg(&g_md2[k]);
        db  += (double)__ldcg(&g_mb[k]);
    }
    #pragma unroll
    for (int o = 16; o > 0; o >>= 1) {
        dsi += __shfl_down_sync(0xffffffffu, dsi, o);
        ci  += __shfl_down_sync(0xffffffffu, ci,  o);
        ds  += __shfl_down_sync(0xffffffffu, ds,  o);
        ds2 += __shfl_down_sync(0xffffffffu, ds2, o);
        db  += __shfl_down_sync(0xffffffffu, db,  o);
    }
    __shared__ double    shd[4][TPB / 32];
    __shared__ long long shl[TPB / 32];
    if (lane == 0) {
        shd[0][wrp] = dsi; shd[1][wrp] = ds; shd[2][wrp] = ds2; shd[3][wrp] = db;
        shl[wrp] = ci;
    }
    __syncthreads();
    if (tid == 0) {
        double Sinv = 0.0, Sd = 0.0, Sd2 = 0.0, Sb = 0.0; long long Cinv = 0;
        #pragma unroll
        for (int w = 0; w < TPB / 32; ++w) {
            Sinv += shd[0][w]; Sd += shd[1][w]; Sd2 += shd[2][w]; Sb += shd[3][w];
            Cinv += shl[w];
        }
        double S_all = 2.0 * (double)NELEM * Sd2 - 2.0 * Sd * Sd;
        long long Cval = (long long)NELEM * (long long)NELEM - Cinv;
        float bce = (float)(Sb / (double)NELEM);
        int bce_only = (flag != nullptr) ? *flag : 0;
        float result;
        if (bce_only) {
            result = bce;
        } else {
            double Sval = S_all - Sinv;
            if (Sval < 0.0) Sval = 0.0;
            double mse = Sval / (double)(Cval > 0 ? Cval : 1);
            result = (Cval > 0) ? (bce + MSEW * (float)mse) : bce;
        }
        out[0] = result;
        g_bar1 = 0u;
        g_bar2 = 0u;
    }
    for (int k = tid; k < NB; k += TPB) g_bcnt[k] = 0;   // reset for next replay
}

extern "C" void kernel_launch(void* const* d_in, const int* in_sizes, int n_in,
                              void* d_out, int out_size) {
    const float* pred = (const float*)d_in[0];
    const float* psi  = (const float*)d_in[1];
    const int*   flag = (n_in >= 3 && in_sizes[2] >= 1) ? (const int*)d_in[2] : nullptr;

    fused<<<NBLK, TPB>>>(pred, psi, flag, (float*)d_out);
}